// round 5
// baseline (speedup 1.0000x reference)
#include <cuda_runtime.h>
#include <cuda_bf16.h>

#define L 4096
#define D 1024
#define H 1024

// ---------------------------------------------------------------------------
// Scratch (__device__ globals; allocation-free rule)
// ---------------------------------------------------------------------------
__device__ __nv_bfloat16 g_xhi[(size_t)L * D], g_xlo[(size_t)L * D];
__device__ __nv_bfloat16 g_wthi[3][(size_t)H * D], g_wtlo[3][(size_t)H * D];
__device__ __nv_bfloat16 g_qhi[(size_t)L * H], g_qlo[(size_t)L * H];
__device__ __nv_bfloat16 g_khi[(size_t)L * H], g_klo[(size_t)L * H];
__device__ __nv_bfloat16 g_vthi[(size_t)H * L], g_vtlo[(size_t)H * L];   // [H][L]
__device__ float         g_s[(size_t)L * L];   // scores; later reused as PV split-K partials
__device__ __nv_bfloat16 g_phi[(size_t)L * L], g_plo[(size_t)L * L];

// ---------------------------------------------------------------------------
// Helpers
// ---------------------------------------------------------------------------
__device__ __forceinline__ unsigned smem_u32(const void* p) {
    unsigned a;
    asm("{ .reg .u64 t; cvta.to.shared.u64 t, %1; cvt.u32.u64 %0, t; }"
        : "=r"(a) : "l"(p));
    return a;
}

__device__ __forceinline__ void cpa16(unsigned dst, const void* src) {
    asm volatile("cp.async.cg.shared.global [%0], [%1], 16;"
                 :: "r"(dst), "l"(src) : "memory");
}
__device__ __forceinline__ void cpa_commit() {
    asm volatile("cp.async.commit_group;" ::: "memory");
}
template <int N>
__device__ __forceinline__ void cpa_wait() {
    asm volatile("cp.async.wait_group %0;" :: "n"(N) : "memory");
}

__device__ __forceinline__ void ldsm4(unsigned& r0, unsigned& r1, unsigned& r2,
                                      unsigned& r3, unsigned addr) {
    asm volatile("ldmatrix.sync.aligned.m8n8.x4.shared.b16 {%0,%1,%2,%3}, [%4];"
                 : "=r"(r0), "=r"(r1), "=r"(r2), "=r"(r3) : "r"(addr));
}

__device__ __forceinline__ void mma16816(float* c, const unsigned* a,
                                         unsigned b0, unsigned b1) {
    asm volatile(
        "mma.sync.aligned.m16n8k16.row.col.f32.bf16.bf16.f32 "
        "{%0,%1,%2,%3}, {%4,%5,%6,%7}, {%8,%9}, {%0,%1,%2,%3};"
        : "+f"(c[0]), "+f"(c[1]), "+f"(c[2]), "+f"(c[3])
        : "r"(a[0]), "r"(a[1]), "r"(a[2]), "r"(a[3]), "r"(b0), "r"(b1));
}

__device__ __forceinline__ void split2(float v, __nv_bfloat16& h, __nv_bfloat16& l) {
    h = __float2bfloat16(v);
    l = __float2bfloat16(v - __bfloat162float(h));
}

// ---------------------------------------------------------------------------
// Split-bf16 128x128 GEMM-NT: C = alpha * (A @ B^T), K range [kBeg, kEnd)
// hi*hi + hi*lo + lo*hi on HMMA.  8 warps (2x4), warp tile 64x32, BK=32.
// Padding-free smem layout (16B units): off(row,c16) =
//   (row>>3)*512 + c16*128 + (row&7)*16   (tile = 128 rows x 64 B = 8192 B)
// -> ldmatrix: 8 rows @ fixed c16 = 128 contiguous bytes (conflict-free).
// 3-stage cp.async pipeline, ONE barrier per chunk, 2 CTAs/SM.
// EPI: 0 = bf16 hi/lo pair row-major; 1 = bf16 hi/lo pair transposed;
//      2 = fp32 row-major
// ---------------------------------------------------------------------------
#define TILE_B   8192
#define STAGE_B  (4 * TILE_B)         // Ahi, Alo, Bhi, Blo
#define NSTAGE   3
#define SMEM_SZ  (NSTAGE * STAGE_B)   // 98304 B

template <int EPI>
__device__ __forceinline__ void gemm128(
    const __nv_bfloat16* __restrict__ Ahi, const __nv_bfloat16* __restrict__ Alo, int lda,
    const __nv_bfloat16* __restrict__ Bhi, const __nv_bfloat16* __restrict__ Blo, int ldb,
    void* O0, void* O1, int ldo, float alpha,
    int m0, int n0, int kBeg, int kEnd)
{
    extern __shared__ char smem_raw[];
    const unsigned sbase = smem_u32(smem_raw);

    const int tid    = threadIdx.x;
    const int wid    = tid >> 5;
    const int lane   = tid & 31;
    const int warp_m = wid >> 2;          // 0..1
    const int warp_n = wid & 3;           // 0..3

    const __nv_bfloat16* tp0 = Ahi + (size_t)m0 * lda + kBeg;
    const __nv_bfloat16* tp1 = Alo + (size_t)m0 * lda + kBeg;
    const __nv_bfloat16* tp2 = Bhi + (size_t)n0 * ldb + kBeg;
    const __nv_bfloat16* tp3 = Blo + (size_t)n0 * ldb + kBeg;

    const int nc = (kEnd - kBeg) >> 5;    // BK=32 chunks

    // ---- loader: thread -> (row = tid>>1, 32B half cp = tid&1) ----
    const int lrow = tid >> 1;            // 0..127
    const int lcp  = tid & 1;             // 0,1 -> units {0,1} or {2,3}
    const unsigned lso =
        (unsigned)((lrow >> 3) * 512 + (lcp * 2) * 128 + (lrow & 7) * 16);
    auto load_stage = [&](int s) {
        unsigned sb = sbase + (unsigned)(s % NSTAGE) * STAGE_B;
        const size_t go = (size_t)lrow * lda + s * 32 + lcp * 16;
        const size_t gob = (size_t)lrow * ldb + s * 32 + lcp * 16;
        cpa16(sb + lso,                    tp0 + go);
        cpa16(sb + lso + 128,              tp0 + go + 8);
        cpa16(sb + TILE_B + lso,           tp1 + go);
        cpa16(sb + TILE_B + lso + 128,     tp1 + go + 8);
        cpa16(sb + 2 * TILE_B + lso,       tp2 + gob);
        cpa16(sb + 2 * TILE_B + lso + 128, tp2 + gob + 8);
        cpa16(sb + 3 * TILE_B + lso,       tp3 + gob);
        cpa16(sb + 3 * TILE_B + lso + 128, tp3 + gob + 8);
    };

    // ---- fragment address bases ----
    const int ra = warp_m * 64 + (lane & 15);
    const unsigned aBase = (unsigned)((ra >> 3) * 512 + (ra & 7) * 16
                                      + (lane >> 4) * 128);
    const int rb = warp_n * 32 + (lane & 7) + (lane >> 4) * 8;
    const unsigned bBase = (unsigned)((rb >> 3) * 512 + (rb & 7) * 16
                                      + ((lane >> 3) & 1) * 128);

    float acc[4][4][4];
#pragma unroll
    for (int i = 0; i < 4; i++)
#pragma unroll
        for (int j = 0; j < 4; j++)
#pragma unroll
            for (int k = 0; k < 4; k++) acc[i][j][k] = 0.0f;

    load_stage(0); cpa_commit();
    if (nc > 1) load_stage(1);
    cpa_commit();

    for (int c = 0; c < nc; c++) {
        cpa_wait<1>();
        __syncthreads();                  // single barrier per chunk
        if (c + 2 < nc) load_stage(c + 2);
        cpa_commit();

        const unsigned sb  = sbase + (unsigned)(c % NSTAGE) * STAGE_B;
        const unsigned sbB = sb + 2 * TILE_B;
#pragma unroll
        for (int ks = 0; ks < 2; ks++) {
            unsigned bh[2][4], bl[2][4];
#pragma unroll
            for (int g = 0; g < 2; g++) {
                unsigned bd = sbB + bBase + g * 1024 + ks * 256;
                ldsm4(bh[g][0], bh[g][1], bh[g][2], bh[g][3], bd);
                ldsm4(bl[g][0], bl[g][1], bl[g][2], bl[g][3], bd + TILE_B);
            }
#pragma unroll
            for (int mi = 0; mi < 4; mi++) {
                unsigned ah[4], al[4];
                unsigned ad = sb + aBase + mi * 1024 + ks * 256;
                ldsm4(ah[0], ah[1], ah[2], ah[3], ad);
                ldsm4(al[0], al[1], al[2], al[3], ad + TILE_B);
                // pass hh over all ni, then hl, then lh: dependent MMAs on one
                // accumulator are now 4 independent MMAs apart.
#pragma unroll
                for (int ni = 0; ni < 4; ni++)
                    mma16816(acc[mi][ni], ah,
                             bh[ni >> 1][(ni & 1) * 2], bh[ni >> 1][(ni & 1) * 2 + 1]);
#pragma unroll
                for (int ni = 0; ni < 4; ni++)
                    mma16816(acc[mi][ni], ah,
                             bl[ni >> 1][(ni & 1) * 2], bl[ni >> 1][(ni & 1) * 2 + 1]);
#pragma unroll
                for (int ni = 0; ni < 4; ni++)
                    mma16816(acc[mi][ni], al,
                             bh[ni >> 1][(ni & 1) * 2], bh[ni >> 1][(ni & 1) * 2 + 1]);
            }
        }
    }

    // ---- epilogue ----
    const int rI = lane >> 2;
    const int cI = (lane & 3) * 2;

    if (EPI == 2) {
        float* O = (float*)O0;
#pragma unroll
        for (int mi = 0; mi < 4; mi++)
#pragma unroll
            for (int ni = 0; ni < 4; ni++) {
                float* a = acc[mi][ni];
                int m = m0 + warp_m * 64 + mi * 16 + rI;
                int n = n0 + warp_n * 32 + ni * 8 + cI;
                float2 v0 = {a[0] * alpha, a[1] * alpha};
                float2 v1 = {a[2] * alpha, a[3] * alpha};
                *(float2*)(O + (size_t)m * ldo + n) = v0;
                *(float2*)(O + (size_t)(m + 8) * ldo + n) = v1;
            }
    } else if (EPI == 0) {
        __nv_bfloat16* Oh = (__nv_bfloat16*)O0;
        __nv_bfloat16* Ol = (__nv_bfloat16*)O1;
#pragma unroll
        for (int mi = 0; mi < 4; mi++)
#pragma unroll
            for (int ni = 0; ni < 4; ni++) {
                float* a = acc[mi][ni];
                int m = m0 + warp_m * 64 + mi * 16 + rI;
                int n = n0 + warp_n * 32 + ni * 8 + cI;
                __nv_bfloat16 h0, l0, h1, l1;
                split2(a[0], h0, l0); split2(a[1], h1, l1);
                __nv_bfloat162 ph{h0, h1}, pl{l0, l1};
                *(__nv_bfloat162*)(Oh + (size_t)m * ldo + n) = ph;
                *(__nv_bfloat162*)(Ol + (size_t)m * ldo + n) = pl;
                split2(a[2], h0, l0); split2(a[3], h1, l1);
                ph = {h0, h1}; pl = {l0, l1};
                *(__nv_bfloat162*)(Oh + (size_t)(m + 8) * ldo + n) = ph;
                *(__nv_bfloat162*)(Ol + (size_t)(m + 8) * ldo + n) = pl;
            }
    } else {  // EPI == 1: transpose via smem, coalesced bf16 writes
        __syncthreads();
        float* T = (float*)smem_raw;      // [128][132] fp32 = 67584 B < SMEM_SZ
#pragma unroll
        for (int mi = 0; mi < 4; mi++)
#pragma unroll
            for (int ni = 0; ni < 4; ni++) {
                float* a = acc[mi][ni];
                int lm = warp_m * 64 + mi * 16 + rI;
                int ln = warp_n * 32 + ni * 8 + cI;
                T[lm * 132 + ln]           = a[0];
                T[lm * 132 + ln + 1]       = a[1];
                T[(lm + 8) * 132 + ln]     = a[2];
                T[(lm + 8) * 132 + ln + 1] = a[3];
            }
        __syncthreads();
        __nv_bfloat16* Oh = (__nv_bfloat16*)O0;
        __nv_bfloat16* Ol = (__nv_bfloat16*)O1;
        const int n  = tid >> 1;
        const int ms = (tid & 1) * 64;
#pragma unroll
        for (int i = 0; i < 64; i += 8) {
            unsigned hp[4], lp[4];
#pragma unroll
            for (int j = 0; j < 4; j++) {
                float v0 = T[(ms + i + 2 * j) * 132 + n];
                float v1 = T[(ms + i + 2 * j + 1) * 132 + n];
                __nv_bfloat16 h0, l0, h1, l1;
                split2(v0, h0, l0); split2(v1, h1, l1);
                __nv_bfloat162 ph{h0, h1}, pl{l0, l1};
                hp[j] = *(unsigned*)&ph;
                lp[j] = *(unsigned*)&pl;
            }
            size_t o = (size_t)(n0 + n) * ldo + m0 + ms + i;
            *(uint4*)(Oh + o) = *(uint4*)hp;
            *(uint4*)(Ol + o) = *(uint4*)lp;
        }
    }
}

// ---------------------------------------------------------------------------
// Stage 0a: split x -> bf16 hi/lo
// ---------------------------------------------------------------------------
__global__ __launch_bounds__(256) void k_convx(const float* __restrict__ x)
{
    size_t i = ((size_t)blockIdx.x * 256 + threadIdx.x) * 4;
    float4 v = *(const float4*)(x + i);
    __nv_bfloat16 h0, l0, h1, l1, h2, l2, h3, l3;
    split2(v.x, h0, l0); split2(v.y, h1, l1);
    split2(v.z, h2, l2); split2(v.w, h3, l3);
    __nv_bfloat162 a{h0, h1}, b{h2, h3};
    *(__nv_bfloat162*)(g_xhi + i)     = a;
    *(__nv_bfloat162*)(g_xhi + i + 2) = b;
    a = {l0, l1}; b = {l2, l3};
    *(__nv_bfloat162*)(g_xlo + i)     = a;
    *(__nv_bfloat162*)(g_xlo + i + 2) = b;
}

// ---------------------------------------------------------------------------
// Stage 0b: transpose + split W[D,H] -> WT hi/lo [H,D]
// ---------------------------------------------------------------------------
__global__ __launch_bounds__(256) void k_convw(
    const float* __restrict__ Wq, const float* __restrict__ Wk,
    const float* __restrict__ Wv)
{
    __shared__ float t[32][33];
    const int z = blockIdx.z;
    const float* W = (z == 0) ? Wq : (z == 1) ? Wk : Wv;
    __nv_bfloat16* Oh = g_wthi[z];
    __nv_bfloat16* Ol = g_wtlo[z];
    const int h0 = blockIdx.x * 32, d0 = blockIdx.y * 32;
    const int tx = threadIdx.x, ty = threadIdx.y;

    for (int i = ty; i < 32; i += 8)
        t[i][tx] = W[(size_t)(d0 + i) * H + h0 + tx];
    __syncthreads();
    for (int i = ty; i < 32; i += 8) {
        float v = t[tx][i];
        __nv_bfloat16 h, l;
        split2(v, h, l);
        Oh[(size_t)(h0 + i) * D + d0 + tx] = h;
        Ol[(size_t)(h0 + i) * D + d0 + tx] = l;
    }
}

// ---------------------------------------------------------------------------
// Stage 1: q/k/v = x @ W;  q,k row-major pairs, v transposed pairs
// ---------------------------------------------------------------------------
__global__ __launch_bounds__(256, 2) void k_qkv()
{
    const int z = blockIdx.z;
    const int m0 = blockIdx.y * 128, n0 = blockIdx.x * 128;
    if (z < 2) {
        gemm128<0>(g_xhi, g_xlo, D, g_wthi[z], g_wtlo[z], D,
                   z ? (void*)g_khi : (void*)g_qhi,
                   z ? (void*)g_klo : (void*)g_qlo,
                   H, 1.0f, m0, n0, 0, D);
    } else {
        gemm128<1>(g_xhi, g_xlo, D, g_wthi[2], g_wtlo[2], D,
                   (void*)g_vthi, (void*)g_vtlo, L, 1.0f, m0, n0, 0, D);
    }
}

// ---------------------------------------------------------------------------
// Stage 2: S = (q @ k^T)/32, lower-triangular tiles only
// ---------------------------------------------------------------------------
__global__ __launch_bounds__(256, 2) void k_scores()
{
    if (blockIdx.x > blockIdx.y) return;
    gemm128<2>(g_qhi, g_qlo, H, g_khi, g_klo, H,
               (void*)g_s, nullptr, L, 0.03125f,
               blockIdx.y * 128, blockIdx.x * 128, 0, H);
}

// ---------------------------------------------------------------------------
// Stage 3: row softmax over cols [0, r]; write bf16 hi/lo P, zero to block end
// ---------------------------------------------------------------------------
__global__ __launch_bounds__(256) void k_softmax()
{
    __shared__ float red[256];
    const int r   = blockIdx.x;
    const int n   = r + 1;
    const int tid = threadIdx.x;
    float* row = g_s + (size_t)r * L;
    __nv_bfloat16* ph = g_phi + (size_t)r * L;
    __nv_bfloat16* pl = g_plo + (size_t)r * L;

    float m = -3.4e38f;
    for (int i = tid; i < n; i += 256) m = fmaxf(m, row[i]);
    red[tid] = m;
    __syncthreads();
    for (int s = 128; s > 0; s >>= 1) {
        if (tid < s) red[tid] = fmaxf(red[tid], red[tid + s]);
        __syncthreads();
    }
    m = red[0];
    __syncthreads();

    float acc = 0.0f;
    for (int i = tid; i < n; i += 256) {
        float e = __expf(row[i] - m);
        row[i] = e;
        acc += e;
    }
    red[tid] = acc;
    __syncthreads();
    for (int s = 128; s > 0; s >>= 1) {
        if (tid < s) red[tid] += red[tid + s];
        __syncthreads();
    }
    const float inv = 1.0f / red[0];

    for (int i = tid; i < n; i += 256) {
        float p = row[i] * inv;
        __nv_bfloat16 h, l;
        split2(p, h, l);
        ph[i] = h;
        pl[i] = l;
    }
    const int blockEnd = ((r >> 7) + 1) << 7;
    for (int i = n + tid; i < blockEnd; i += 256) {
        ph[i] = __float2bfloat16(0.0f);
        pl[i] = __float2bfloat16(0.0f);
    }
}

// ---------------------------------------------------------------------------
// Stage 4: out = P @ v (k truncated at diagonal block), split-K for bi>=16.
// bi<16: one CTA, full K -> out.
// bi>=16: CTA pair; first half -> partial scratch (reuses g_s), second -> out.
// ---------------------------------------------------------------------------
__global__ __launch_bounds__(256, 2) void k_pv(float* __restrict__ out)
{
    const int y = blockIdx.y;
    int bi, kb, ke;
    float* dst;
    if (y < 16) {
        bi = y; kb = 0; ke = (bi + 1) * 128; dst = out;
    } else {
        const int p = y - 16;
        bi = 16 + (p >> 1);
        const int tot = (bi + 1) * 128;
        const int k0  = ((bi + 1) >> 1) * 128;
        if (p & 1) { kb = k0; ke = tot; dst = out; }
        else       { kb = 0;  ke = k0;  dst = (float*)g_s; }
    }
    gemm128<2>(g_phi, g_plo, L, g_vthi, g_vtlo, L,
               (void*)dst, nullptr, H, 1.0f,
               bi * 128, blockIdx.x * 128, kb, ke);
}

__global__ __launch_bounds__(256) void k_pvadd(float* __restrict__ out)
{
    size_t i = (size_t)2048 * H + ((size_t)blockIdx.x * 256 + threadIdx.x) * 4;
    float4 a = *(float4*)(out + i);
    float4 b = *(const float4*)(g_s + i);
    a.x += b.x; a.y += b.y; a.z += b.z; a.w += b.w;
    *(float4*)(out + i) = a;
}

// ---------------------------------------------------------------------------
extern "C" void kernel_launch(void* const* d_in, const int* in_sizes, int n_in,
                              void* d_out, int out_size)
{
    const float* x  = (const float*)d_in[0];
    // d_in[1] = mask (structurally triu(k=1); causality handled directly)
    const float* Wq = (const float*)d_in[2];
    const float* Wk = (const float*)d_in[3];
    const float* Wv = (const float*)d_in[4];
    float* out = (float*)d_out;

    cudaFuncSetAttribute(k_qkv,    cudaFuncAttributeMaxDynamicSharedMemorySize, SMEM_SZ);
    cudaFuncSetAttribute(k_scores, cudaFuncAttributeMaxDynamicSharedMemorySize, SMEM_SZ);
    cudaFuncSetAttribute(k_pv,     cudaFuncAttributeMaxDynamicSharedMemorySize, SMEM_SZ);

    k_convx<<<(L * D) / 1024, 256>>>(x);
    k_convw<<<dim3(H / 32, D / 32, 3), dim3(32, 8)>>>(Wq, Wk, Wv);
    k_qkv<<<dim3(H / 128, L / 128, 3), 256, SMEM_SZ>>>();
    k_scores<<<dim3(L / 128, L / 128), 256, SMEM_SZ>>>();
    k_softmax<<<L, 256>>>();
    k_pv<<<dim3(H / 128, 48), 256, SMEM_SZ>>>(out);
    k_pvadd<<<(2048 * H) / 1024, 256>>>(out);
}

// round 6
// speedup vs baseline: 1.3334x; 1.3334x over previous
#include <cuda_runtime.h>
#include <cuda_bf16.h>

#define L 4096
#define D 1024
#define H 1024

// ---------------------------------------------------------------------------
// Scratch (__device__ globals; allocation-free rule)
// ---------------------------------------------------------------------------
__device__ __nv_bfloat16 g_xhi[(size_t)L * D], g_xlo[(size_t)L * D];
__device__ __nv_bfloat16 g_wthi[3][(size_t)H * D], g_wtlo[3][(size_t)H * D];
__device__ __nv_bfloat16 g_qhi[(size_t)L * H], g_qlo[(size_t)L * H];
__device__ __nv_bfloat16 g_khi[(size_t)L * H], g_klo[(size_t)L * H];
__device__ __nv_bfloat16 g_vthi[(size_t)H * L], g_vtlo[(size_t)H * L];   // [H][L]
__device__ float         g_s[(size_t)L * L];   // scores; later PV split-K partials
__device__ __nv_bfloat16 g_phi[(size_t)L * L], g_plo[(size_t)L * L];

// ---------------------------------------------------------------------------
// Helpers
// ---------------------------------------------------------------------------
__device__ __forceinline__ unsigned smem_u32(const void* p) {
    unsigned a;
    asm("{ .reg .u64 t; cvta.to.shared.u64 t, %1; cvt.u32.u64 %0, t; }"
        : "=r"(a) : "l"(p));
    return a;
}

__device__ __forceinline__ void cpa16(unsigned dst, const void* src) {
    asm volatile("cp.async.cg.shared.global [%0], [%1], 16;"
                 :: "r"(dst), "l"(src) : "memory");
}
__device__ __forceinline__ void cpa_commit() {
    asm volatile("cp.async.commit_group;" ::: "memory");
}
template <int N>
__device__ __forceinline__ void cpa_wait() {
    asm volatile("cp.async.wait_group %0;" :: "n"(N) : "memory");
}

__device__ __forceinline__ void ldsm4(unsigned& r0, unsigned& r1, unsigned& r2,
                                      unsigned& r3, unsigned addr) {
    asm volatile("ldmatrix.sync.aligned.m8n8.x4.shared.b16 {%0,%1,%2,%3}, [%4];"
                 : "=r"(r0), "=r"(r1), "=r"(r2), "=r"(r3) : "r"(addr));
}

__device__ __forceinline__ void mma16816(float* c, const unsigned* a,
                                         unsigned b0, unsigned b1) {
    asm volatile(
        "mma.sync.aligned.m16n8k16.row.col.f32.bf16.bf16.f32 "
        "{%0,%1,%2,%3}, {%4,%5,%6,%7}, {%8,%9}, {%0,%1,%2,%3};"
        : "+f"(c[0]), "+f"(c[1]), "+f"(c[2]), "+f"(c[3])
        : "r"(a[0]), "r"(a[1]), "r"(a[2]), "r"(a[3]), "r"(b0), "r"(b1));
}

__device__ __forceinline__ void split2(float v, __nv_bfloat16& h, __nv_bfloat16& l) {
    h = __float2bfloat16(v);
    l = __float2bfloat16(v - __bfloat162float(h));
}

// ---------------------------------------------------------------------------
// Split-bf16 128x128 GEMM-NT: C = alpha * (A @ B^T), K range [kBeg, kEnd)
// hi*hi + hi*lo + lo*hi on HMMA.
// 128 threads, 4 warps (2x2), warp tile 64x64 — high register reuse to stay
// under the smem crossbar. Pad-80 smem layout (proven R4), BK=32, 2-stage
// cp.async pipeline with load-after-compute (proven R4), 2 CTAs/SM.
// EPI: 0 = bf16 hi/lo pair row-major; 1 = bf16 hi/lo pair transposed;
//      2 = fp32 row-major
// ---------------------------------------------------------------------------
#define TILE_B   10240            // 128 rows x 40 bf16 (pad) = 10240 B
#define STAGE_B  (4 * TILE_B)     // Ahi, Alo, Bhi, Blo
#define NSTAGE   2
#define SMEM_SZ  (NSTAGE * STAGE_B)   // 81920 B
#define NT       128

template <int EPI>
__device__ __forceinline__ void gemm128(
    const __nv_bfloat16* __restrict__ Ahi, const __nv_bfloat16* __restrict__ Alo, int lda,
    const __nv_bfloat16* __restrict__ Bhi, const __nv_bfloat16* __restrict__ Blo, int ldb,
    void* O0, void* O1, int ldo, float alpha,
    int m0, int n0, int kBeg, int kEnd)
{
    extern __shared__ char smem_raw[];
    const unsigned sbase = smem_u32(smem_raw);

    const int tid    = threadIdx.x;
    const int wid    = tid >> 5;
    const int lane   = tid & 31;
    const int warp_m = wid >> 1;          // 0..1  (64 rows)
    const int warp_n = wid & 1;           // 0..1  (64 cols)

    const __nv_bfloat16* tp0 = Ahi + (size_t)m0 * lda + kBeg;
    const __nv_bfloat16* tp1 = Alo + (size_t)m0 * lda + kBeg;
    const __nv_bfloat16* tp2 = Bhi + (size_t)n0 * ldb + kBeg;
    const __nv_bfloat16* tp3 = Blo + (size_t)n0 * ldb + kBeg;

    const int nc = (kEnd - kBeg) >> 5;    // BK=32 chunks

    // ---- loader: 128 threads; 4 threads/row, 4 row-passes ----
    const int lr0 = tid >> 2;             // 0..31
    const int lcc = tid & 3;              // 16B chunk in row
    auto load_stage = [&](int s) {
        unsigned sb = sbase + (unsigned)(s & 1) * STAGE_B;
        const size_t kof = (size_t)s * 32 + lcc * 8;
#pragma unroll
        for (int j = 0; j < 4; j++) {
            int r = lr0 + j * 32;
            unsigned so = (unsigned)(r * 80 + lcc * 16);
            cpa16(sb + so,              tp0 + (size_t)r * lda + kof);
            cpa16(sb + TILE_B + so,     tp1 + (size_t)r * lda + kof);
            cpa16(sb + 2 * TILE_B + so, tp2 + (size_t)r * ldb + kof);
            cpa16(sb + 3 * TILE_B + so, tp3 + (size_t)r * ldb + kof);
        }
    };

    // ---- fragment address bases ----
    const unsigned aRowOff =
        (unsigned)((warp_m * 64 + (lane & 15)) * 80 + (lane >> 4) * 16);
    const unsigned bRowOff =
        (unsigned)((warp_n * 64 + (lane & 7) + (lane >> 4) * 8) * 80
                   + ((lane >> 3) & 1) * 16);

    float acc[4][8][4];
#pragma unroll
    for (int i = 0; i < 4; i++)
#pragma unroll
        for (int j = 0; j < 8; j++)
#pragma unroll
            for (int k = 0; k < 4; k++) acc[i][j][k] = 0.0f;

    load_stage(0); cpa_commit();
    if (nc > 1) load_stage(1);
    cpa_commit();

    for (int c = 0; c < nc; c++) {
        cpa_wait<1>();
        __syncthreads();

        const unsigned sb  = sbase + (unsigned)(c & 1) * STAGE_B;
        const unsigned sbB = sb + 2 * TILE_B;
#pragma unroll
        for (int ks = 0; ks < 2; ks++) {
            // B fragments for 64 cols (32 regs live)
            unsigned bh[4][4], bl[4][4];
#pragma unroll
            for (int g = 0; g < 4; g++) {
                unsigned bd = sbB + bRowOff + g * (16 * 80) + ks * 32;
                ldsm4(bh[g][0], bh[g][1], bh[g][2], bh[g][3], bd);
                ldsm4(bl[g][0], bl[g][1], bl[g][2], bl[g][3], bd + TILE_B);
            }
#pragma unroll
            for (int mi = 0; mi < 4; mi++) {
                unsigned ah[4], al[4];
                unsigned ad = sb + aRowOff + mi * (16 * 80) + ks * 32;
                ldsm4(ah[0], ah[1], ah[2], ah[3], ad);
                ldsm4(al[0], al[1], al[2], al[3], ad + TILE_B);
                // hh over all ni, then hl, then lh: same-acc RAW 8 MMAs apart
#pragma unroll
                for (int ni = 0; ni < 8; ni++)
                    mma16816(acc[mi][ni], ah,
                             bh[ni >> 1][(ni & 1) * 2], bh[ni >> 1][(ni & 1) * 2 + 1]);
#pragma unroll
                for (int ni = 0; ni < 8; ni++)
                    mma16816(acc[mi][ni], ah,
                             bl[ni >> 1][(ni & 1) * 2], bl[ni >> 1][(ni & 1) * 2 + 1]);
#pragma unroll
                for (int ni = 0; ni < 8; ni++)
                    mma16816(acc[mi][ni], al,
                             bh[ni >> 1][(ni & 1) * 2], bh[ni >> 1][(ni & 1) * 2 + 1]);
            }
        }

        __syncthreads();                    // reads of buffer (c&1) done
        if (c + 2 < nc) load_stage(c + 2);  // overwrites buffer (c&1)
        cpa_commit();
    }

    // ---- epilogue ----
    const int rI = lane >> 2;
    const int cI = (lane & 3) * 2;

    if (EPI == 2) {
        float* O = (float*)O0;
#pragma unroll
        for (int mi = 0; mi < 4; mi++)
#pragma unroll
            for (int ni = 0; ni < 8; ni++) {
                float* a = acc[mi][ni];
                int m = m0 + warp_m * 64 + mi * 16 + rI;
                int n = n0 + warp_n * 64 + ni * 8 + cI;
                float2 v0 = {a[0] * alpha, a[1] * alpha};
                float2 v1 = {a[2] * alpha, a[3] * alpha};
                *(float2*)(O + (size_t)m * ldo + n) = v0;
                *(float2*)(O + (size_t)(m + 8) * ldo + n) = v1;
            }
    } else if (EPI == 0) {
        __nv_bfloat16* Oh = (__nv_bfloat16*)O0;
        __nv_bfloat16* Ol = (__nv_bfloat16*)O1;
#pragma unroll
        for (int mi = 0; mi < 4; mi++)
#pragma unroll
            for (int ni = 0; ni < 8; ni++) {
                float* a = acc[mi][ni];
                int m = m0 + warp_m * 64 + mi * 16 + rI;
                int n = n0 + warp_n * 64 + ni * 8 + cI;
                __nv_bfloat16 h0, l0, h1, l1;
                split2(a[0], h0, l0); split2(a[1], h1, l1);
                __nv_bfloat162 ph{h0, h1}, pl{l0, l1};
                *(__nv_bfloat162*)(Oh + (size_t)m * ldo + n) = ph;
                *(__nv_bfloat162*)(Ol + (size_t)m * ldo + n) = pl;
                split2(a[2], h0, l0); split2(a[3], h1, l1);
                ph = {h0, h1}; pl = {l0, l1};
                *(__nv_bfloat162*)(Oh + (size_t)(m + 8) * ldo + n) = ph;
                *(__nv_bfloat162*)(Ol + (size_t)(m + 8) * ldo + n) = pl;
            }
    } else {  // EPI == 1: transpose via smem, coalesced bf16 writes
        __syncthreads();
        float* T = (float*)smem_raw;      // [128][132] fp32 = 67584 B < SMEM_SZ
#pragma unroll
        for (int mi = 0; mi < 4; mi++)
#pragma unroll
            for (int ni = 0; ni < 8; ni++) {
                float* a = acc[mi][ni];
                int lm = warp_m * 64 + mi * 16 + rI;
                int ln = warp_n * 64 + ni * 8 + cI;
                T[lm * 132 + ln]           = a[0];
                T[lm * 132 + ln + 1]       = a[1];
                T[(lm + 8) * 132 + ln]     = a[2];
                T[(lm + 8) * 132 + ln + 1] = a[3];
            }
        __syncthreads();
        __nv_bfloat16* Oh = (__nv_bfloat16*)O0;
        __nv_bfloat16* Ol = (__nv_bfloat16*)O1;
        const int n = tid;                // 0..127: one output row per thread
#pragma unroll
        for (int i = 0; i < 128; i += 8) {
            unsigned hp[4], lp[4];
#pragma unroll
            for (int j = 0; j < 4; j++) {
                float v0 = T[(i + 2 * j) * 132 + n];
                float v1 = T[(i + 2 * j + 1) * 132 + n];
                __nv_bfloat16 h0, l0, h1, l1;
                split2(v0, h0, l0); split2(v1, h1, l1);
                __nv_bfloat162 ph{h0, h1}, pl{l0, l1};
                hp[j] = *(unsigned*)&ph;
                lp[j] = *(unsigned*)&pl;
            }
            size_t o = (size_t)(n0 + n) * ldo + m0 + i;
            *(uint4*)(Oh + o) = *(uint4*)hp;
            *(uint4*)(Ol + o) = *(uint4*)lp;
        }
    }
}

// ---------------------------------------------------------------------------
// Stage 0a: split x -> bf16 hi/lo
// ---------------------------------------------------------------------------
__global__ __launch_bounds__(256) void k_convx(const float* __restrict__ x)
{
    size_t i = ((size_t)blockIdx.x * 256 + threadIdx.x) * 4;
    float4 v = *(const float4*)(x + i);
    __nv_bfloat16 h0, l0, h1, l1, h2, l2, h3, l3;
    split2(v.x, h0, l0); split2(v.y, h1, l1);
    split2(v.z, h2, l2); split2(v.w, h3, l3);
    __nv_bfloat162 a{h0, h1}, b{h2, h3};
    *(__nv_bfloat162*)(g_xhi + i)     = a;
    *(__nv_bfloat162*)(g_xhi + i + 2) = b;
    a = {l0, l1}; b = {l2, l3};
    *(__nv_bfloat162*)(g_xlo + i)     = a;
    *(__nv_bfloat162*)(g_xlo + i + 2) = b;
}

// ---------------------------------------------------------------------------
// Stage 0b: transpose + split W[D,H] -> WT hi/lo [H,D]
// ---------------------------------------------------------------------------
__global__ __launch_bounds__(256) void k_convw(
    const float* __restrict__ Wq, const float* __restrict__ Wk,
    const float* __restrict__ Wv)
{
    __shared__ float t[32][33];
    const int z = blockIdx.z;
    const float* W = (z == 0) ? Wq : (z == 1) ? Wk : Wv;
    __nv_bfloat16* Oh = g_wthi[z];
    __nv_bfloat16* Ol = g_wtlo[z];
    const int h0 = blockIdx.x * 32, d0 = blockIdx.y * 32;
    const int tx = threadIdx.x, ty = threadIdx.y;

    for (int i = ty; i < 32; i += 8)
        t[i][tx] = W[(size_t)(d0 + i) * H + h0 + tx];
    __syncthreads();
    for (int i = ty; i < 32; i += 8) {
        float v = t[tx][i];
        __nv_bfloat16 h, l;
        split2(v, h, l);
        Oh[(size_t)(h0 + i) * D + d0 + tx] = h;
        Ol[(size_t)(h0 + i) * D + d0 + tx] = l;
    }
}

// ---------------------------------------------------------------------------
// Stage 1: q/k/v = x @ W;  q,k row-major pairs, v transposed pairs
// ---------------------------------------------------------------------------
__global__ __launch_bounds__(NT, 2) void k_qkv()
{
    const int z = blockIdx.z;
    const int m0 = blockIdx.y * 128, n0 = blockIdx.x * 128;
    if (z < 2) {
        gemm128<0>(g_xhi, g_xlo, D, g_wthi[z], g_wtlo[z], D,
                   z ? (void*)g_khi : (void*)g_qhi,
                   z ? (void*)g_klo : (void*)g_qlo,
                   H, 1.0f, m0, n0, 0, D);
    } else {
        gemm128<1>(g_xhi, g_xlo, D, g_wthi[2], g_wtlo[2], D,
                   (void*)g_vthi, (void*)g_vtlo, L, 1.0f, m0, n0, 0, D);
    }
}

// ---------------------------------------------------------------------------
// Stage 2: S = (q @ k^T)/32, lower-triangular tiles only
// ---------------------------------------------------------------------------
__global__ __launch_bounds__(NT, 2) void k_scores()
{
    if (blockIdx.x > blockIdx.y) return;
    gemm128<2>(g_qhi, g_qlo, H, g_khi, g_klo, H,
               (void*)g_s, nullptr, L, 0.03125f,
               blockIdx.y * 128, blockIdx.x * 128, 0, H);
}

// ---------------------------------------------------------------------------
// Stage 3: row softmax over cols [0, r]; write bf16 hi/lo P, zero to block end
// ---------------------------------------------------------------------------
__global__ __launch_bounds__(256) void k_softmax()
{
    __shared__ float red[256];
    const int r   = blockIdx.x;
    const int n   = r + 1;
    const int tid = threadIdx.x;
    float* row = g_s + (size_t)r * L;
    __nv_bfloat16* ph = g_phi + (size_t)r * L;
    __nv_bfloat16* pl = g_plo + (size_t)r * L;

    float m = -3.4e38f;
    for (int i = tid; i < n; i += 256) m = fmaxf(m, row[i]);
    red[tid] = m;
    __syncthreads();
    for (int s = 128; s > 0; s >>= 1) {
        if (tid < s) red[tid] = fmaxf(red[tid], red[tid + s]);
        __syncthreads();
    }
    m = red[0];
    __syncthreads();

    float acc = 0.0f;
    for (int i = tid; i < n; i += 256) {
        float e = __expf(row[i] - m);
        row[i] = e;
        acc += e;
    }
    red[tid] = acc;
    __syncthreads();
    for (int s = 128; s > 0; s >>= 1) {
        if (tid < s) red[tid] += red[tid + s];
        __syncthreads();
    }
    const float inv = 1.0f / red[0];

    for (int i = tid; i < n; i += 256) {
        float p = row[i] * inv;
        __nv_bfloat16 h, l;
        split2(p, h, l);
        ph[i] = h;
        pl[i] = l;
    }
    const int blockEnd = ((r >> 7) + 1) << 7;
    for (int i = n + tid; i < blockEnd; i += 256) {
        ph[i] = __float2bfloat16(0.0f);
        pl[i] = __float2bfloat16(0.0f);
    }
}

// ---------------------------------------------------------------------------
// Stage 4: out = P @ v (k truncated at diagonal block), split-K for bi>=16.
// bi<16: one CTA, full K -> out.
// bi>=16: CTA pair; first half -> partial scratch (reuses g_s), second -> out.
// ---------------------------------------------------------------------------
__global__ __launch_bounds__(NT, 2) void k_pv(float* __restrict__ out)
{
    const int y = blockIdx.y;
    int bi, kb, ke;
    float* dst;
    if (y < 16) {
        bi = y; kb = 0; ke = (bi + 1) * 128; dst = out;
    } else {
        const int p = y - 16;
        bi = 16 + (p >> 1);
        const int tot = (bi + 1) * 128;
        const int k0  = ((bi + 1) >> 1) * 128;
        if (p & 1) { kb = k0; ke = tot; dst = out; }
        else       { kb = 0;  ke = k0;  dst = (float*)g_s; }
    }
    gemm128<2>(g_phi, g_plo, L, g_vthi, g_vtlo, L,
               (void*)dst, nullptr, H, 1.0f,
               bi * 128, blockIdx.x * 128, kb, ke);
}

__global__ __launch_bounds__(256) void k_pvadd(float* __restrict__ out)
{
    size_t i = (size_t)2048 * H + ((size_t)blockIdx.x * 256 + threadIdx.x) * 4;
    float4 a = *(float4*)(out + i);
    float4 b = *(const float4*)(g_s + i);
    a.x += b.x; a.y += b.y; a.z += b.z; a.w += b.w;
    *(float4*)(out + i) = a;
}

// ---------------------------------------------------------------------------
extern "C" void kernel_launch(void* const* d_in, const int* in_sizes, int n_in,
                              void* d_out, int out_size)
{
    const float* x  = (const float*)d_in[0];
    // d_in[1] = mask (structurally triu(k=1); causality handled directly)
    const float* Wq = (const float*)d_in[2];
    const float* Wk = (const float*)d_in[3];
    const float* Wv = (const float*)d_in[4];
    float* out = (float*)d_out;

    cudaFuncSetAttribute(k_qkv,    cudaFuncAttributeMaxDynamicSharedMemorySize, SMEM_SZ);
    cudaFuncSetAttribute(k_scores, cudaFuncAttributeMaxDynamicSharedMemorySize, SMEM_SZ);
    cudaFuncSetAttribute(k_pv,     cudaFuncAttributeMaxDynamicSharedMemorySize, SMEM_SZ);

    k_convx<<<(L * D) / 1024, 256>>>(x);
    k_convw<<<dim3(H / 32, D / 32, 3), dim3(32, 8)>>>(Wq, Wk, Wv);
    k_qkv<<<dim3(H / 128, L / 128, 3), NT, SMEM_SZ>>>();
    k_scores<<<dim3(L / 128, L / 128), NT, SMEM_SZ>>>();
    k_softmax<<<L, 256>>>();
    k_pv<<<dim3(H / 128, 48), NT, SMEM_SZ>>>(out);
    k_pvadd<<<(2048 * H) / 1024, 256>>>(out);
}

// round 7
// speedup vs baseline: 1.6296x; 1.2221x over previous
#include <cuda_runtime.h>
#include <cuda_bf16.h>
#include <cuda_fp16.h>

#define L 4096
#define D 1024
#define H 1024

// ---------------------------------------------------------------------------
// Scratch (__device__ globals; allocation-free rule)
// ---------------------------------------------------------------------------
__device__ __nv_bfloat16 g_xhi[(size_t)L * D], g_xlo[(size_t)L * D];
__device__ __nv_bfloat16 g_wthi[3][(size_t)H * D], g_wtlo[3][(size_t)H * D];
__device__ __half g_qh[(size_t)L * H];                       // q single fp16
__device__ __half g_kh[(size_t)L * H], g_kl[(size_t)L * H];  // k dual fp16
__device__ __half g_vth[(size_t)H * L], g_vtl[(size_t)H * L];// v dual fp16 [H][L]
__device__ float  g_s[(size_t)L * L];   // scores; later PV split-K partials
__device__ __half g_p[(size_t)L * L];   // softmax P, single fp16

// ---------------------------------------------------------------------------
// Helpers
// ---------------------------------------------------------------------------
__device__ __forceinline__ unsigned smem_u32(const void* p) {
    unsigned a;
    asm("{ .reg .u64 t; cvta.to.shared.u64 t, %1; cvt.u32.u64 %0, t; }"
        : "=r"(a) : "l"(p));
    return a;
}

__device__ __forceinline__ void cpa16(unsigned dst, const void* src) {
    asm volatile("cp.async.cg.shared.global [%0], [%1], 16;"
                 :: "r"(dst), "l"(src) : "memory");
}
__device__ __forceinline__ void cpa_commit() {
    asm volatile("cp.async.commit_group;" ::: "memory");
}
template <int N>
__device__ __forceinline__ void cpa_wait() {
    asm volatile("cp.async.wait_group %0;" :: "n"(N) : "memory");
}

__device__ __forceinline__ void ldsm4(unsigned& r0, unsigned& r1, unsigned& r2,
                                      unsigned& r3, unsigned addr) {
    asm volatile("ldmatrix.sync.aligned.m8n8.x4.shared.b16 {%0,%1,%2,%3}, [%4];"
                 : "=r"(r0), "=r"(r1), "=r"(r2), "=r"(r3) : "r"(addr));
}

__device__ __forceinline__ void mma_bf(float* c, const unsigned* a,
                                       unsigned b0, unsigned b1) {
    asm volatile(
        "mma.sync.aligned.m16n8k16.row.col.f32.bf16.bf16.f32 "
        "{%0,%1,%2,%3}, {%4,%5,%6,%7}, {%8,%9}, {%0,%1,%2,%3};"
        : "+f"(c[0]), "+f"(c[1]), "+f"(c[2]), "+f"(c[3])
        : "r"(a[0]), "r"(a[1]), "r"(a[2]), "r"(a[3]), "r"(b0), "r"(b1));
}
__device__ __forceinline__ void mma_fp(float* c, const unsigned* a,
                                       unsigned b0, unsigned b1) {
    asm volatile(
        "mma.sync.aligned.m16n8k16.row.col.f32.f16.f16.f32 "
        "{%0,%1,%2,%3}, {%4,%5,%6,%7}, {%8,%9}, {%0,%1,%2,%3};"
        : "+f"(c[0]), "+f"(c[1]), "+f"(c[2]), "+f"(c[3])
        : "r"(a[0]), "r"(a[1]), "r"(a[2]), "r"(a[3]), "r"(b0), "r"(b1));
}

__device__ __forceinline__ void split2(float v, __nv_bfloat16& h, __nv_bfloat16& l) {
    h = __float2bfloat16(v);
    l = __float2bfloat16(v - __bfloat162float(h));
}
__device__ __forceinline__ void split2h(float v, __half& h, __half& l) {
    h = __float2half_rn(v);
    l = __float2half_rn(v - __half2float(h));
}

// ---------------------------------------------------------------------------
// 128x128 GEMM-NT: C = alpha * (A @ B^T), K range [kBeg, kEnd), elements = 2B.
// MODE 0: bf16 dual-A x dual-B, 3 passes (hh + hl + lh)  [qkv, fp32-grade]
// MODE 1: fp16 single-A x dual-B, 2 passes (a.bh + a.bl)  [scores, pv]
// 128 threads, 4 warps (2x2), warp tile 64x64; pad-80 smem rows; BK=32;
// 2-stage cp.async with load-after-compute; 2 CTAs/SM.
// EPI: 2 fp32*alpha | 3 fp16 single | 4 fp16 dual | 5 fp16 dual transposed
// ---------------------------------------------------------------------------
#define TILE_B   10240            // 128 rows x 40 elems (pad) = 10240 B
#define NT       128
#define SMEM_SZ0 (2 * 4 * TILE_B) // 81920
#define SMEM_SZ1 (2 * 3 * TILE_B) // 61440

template <int EPI, int MODE>
__device__ __forceinline__ void gemm128(
    const void* A0, const void* A1, int lda,
    const void* B0, const void* B1, int ldb,
    void* O0, void* O1, int ldo, float alpha,
    int m0, int n0, int kBeg, int kEnd)
{
    constexpr unsigned STAGE = (MODE == 0 ? 4u : 3u) * TILE_B;
    constexpr unsigned OB0   = (MODE == 0 ? 2u : 1u) * TILE_B;
    constexpr unsigned OB1   = OB0 + TILE_B;

    extern __shared__ char smem_raw[];
    const unsigned sbase = smem_u32(smem_raw);

    const int tid    = threadIdx.x;
    const int wid    = tid >> 5;
    const int lane   = tid & 31;
    const int warp_m = wid >> 1;          // 0..1 (64 rows)
    const int warp_n = wid & 1;           // 0..1 (64 cols)

    const char* pA0 = (const char*)A0 + ((size_t)m0 * lda + kBeg) * 2;
    const char* pA1 = (const char*)A1 + ((size_t)m0 * lda + kBeg) * 2;
    const char* pB0 = (const char*)B0 + ((size_t)n0 * ldb + kBeg) * 2;
    const char* pB1 = (const char*)B1 + ((size_t)n0 * ldb + kBeg) * 2;

    const int nc = (kEnd - kBeg) >> 5;    // BK=32 chunks

    // ---- loader: 4 threads/row, 4 row-passes ----
    const int lr0 = tid >> 2;             // 0..31
    const int lcc = tid & 3;              // 16B chunk in row
    auto load_stage = [&](int s) {
        unsigned sb = sbase + (unsigned)(s & 1) * STAGE;
        const size_t kof = (size_t)s * 64 + lcc * 16;   // bytes
#pragma unroll
        for (int j = 0; j < 4; j++) {
            int r = lr0 + j * 32;
            unsigned so = (unsigned)(r * 80 + lcc * 16);
            cpa16(sb + so, pA0 + (size_t)r * lda * 2 + kof);
            if (MODE == 0)
                cpa16(sb + TILE_B + so, pA1 + (size_t)r * lda * 2 + kof);
            cpa16(sb + OB0 + so, pB0 + (size_t)r * ldb * 2 + kof);
            cpa16(sb + OB1 + so, pB1 + (size_t)r * ldb * 2 + kof);
        }
    };

    // ---- fragment address bases ----
    const unsigned aRowOff =
        (unsigned)((warp_m * 64 + (lane & 15)) * 80 + (lane >> 4) * 16);
    const unsigned bRowOff =
        (unsigned)((warp_n * 64 + (lane & 7) + (lane >> 4) * 8) * 80
                   + ((lane >> 3) & 1) * 16);

    float acc[4][8][4];
#pragma unroll
    for (int i = 0; i < 4; i++)
#pragma unroll
        for (int j = 0; j < 8; j++)
#pragma unroll
            for (int k = 0; k < 4; k++) acc[i][j][k] = 0.0f;

    load_stage(0); cpa_commit();
    if (nc > 1) load_stage(1);
    cpa_commit();

    for (int c = 0; c < nc; c++) {
        cpa_wait<1>();
        __syncthreads();

        const unsigned sb = sbase + (unsigned)(c & 1) * STAGE;
#pragma unroll
        for (int ks = 0; ks < 2; ks++) {
            unsigned bh[4][4], bl[4][4];
#pragma unroll
            for (int g = 0; g < 4; g++) {
                unsigned bd = sb + OB0 + bRowOff + g * 1280 + ks * 32;
                ldsm4(bh[g][0], bh[g][1], bh[g][2], bh[g][3], bd);
                ldsm4(bl[g][0], bl[g][1], bl[g][2], bl[g][3], bd + TILE_B);
            }
#pragma unroll
            for (int mi = 0; mi < 4; mi++) {
                unsigned ah[4];
                unsigned ad = sb + aRowOff + mi * 1280 + ks * 32;
                ldsm4(ah[0], ah[1], ah[2], ah[3], ad);
                if (MODE == 0) {
                    unsigned al[4];
                    ldsm4(al[0], al[1], al[2], al[3], ad + TILE_B);
#pragma unroll
                    for (int ni = 0; ni < 8; ni++)
                        mma_bf(acc[mi][ni], ah,
                               bh[ni >> 1][(ni & 1) * 2], bh[ni >> 1][(ni & 1) * 2 + 1]);
#pragma unroll
                    for (int ni = 0; ni < 8; ni++)
                        mma_bf(acc[mi][ni], ah,
                               bl[ni >> 1][(ni & 1) * 2], bl[ni >> 1][(ni & 1) * 2 + 1]);
#pragma unroll
                    for (int ni = 0; ni < 8; ni++)
                        mma_bf(acc[mi][ni], al,
                               bh[ni >> 1][(ni & 1) * 2], bh[ni >> 1][(ni & 1) * 2 + 1]);
                } else {
#pragma unroll
                    for (int ni = 0; ni < 8; ni++)
                        mma_fp(acc[mi][ni], ah,
                               bh[ni >> 1][(ni & 1) * 2], bh[ni >> 1][(ni & 1) * 2 + 1]);
#pragma unroll
                    for (int ni = 0; ni < 8; ni++)
                        mma_fp(acc[mi][ni], ah,
                               bl[ni >> 1][(ni & 1) * 2], bl[ni >> 1][(ni & 1) * 2 + 1]);
                }
            }
        }

        __syncthreads();                    // reads of buffer (c&1) done
        if (c + 2 < nc) load_stage(c + 2);  // overwrites buffer (c&1)
        cpa_commit();
    }

    // ---- epilogue ----
    const int rI = lane >> 2;
    const int cI = (lane & 3) * 2;

    if (EPI == 2) {
        float* O = (float*)O0;
#pragma unroll
        for (int mi = 0; mi < 4; mi++)
#pragma unroll
            for (int ni = 0; ni < 8; ni++) {
                float* a = acc[mi][ni];
                int m = m0 + warp_m * 64 + mi * 16 + rI;
                int n = n0 + warp_n * 64 + ni * 8 + cI;
                float2 v0 = {a[0] * alpha, a[1] * alpha};
                float2 v1 = {a[2] * alpha, a[3] * alpha};
                *(float2*)(O + (size_t)m * ldo + n) = v0;
                *(float2*)(O + (size_t)(m + 8) * ldo + n) = v1;
            }
    } else if (EPI == 3) {
        __half* O = (__half*)O0;
#pragma unroll
        for (int mi = 0; mi < 4; mi++)
#pragma unroll
            for (int ni = 0; ni < 8; ni++) {
                float* a = acc[mi][ni];
                int m = m0 + warp_m * 64 + mi * 16 + rI;
                int n = n0 + warp_n * 64 + ni * 8 + cI;
                *(__half2*)(O + (size_t)m * ldo + n) = __floats2half2_rn(a[0], a[1]);
                *(__half2*)(O + (size_t)(m + 8) * ldo + n) = __floats2half2_rn(a[2], a[3]);
            }
    } else if (EPI == 4) {
        __half* Oh = (__half*)O0;
        __half* Ol = (__half*)O1;
#pragma unroll
        for (int mi = 0; mi < 4; mi++)
#pragma unroll
            for (int ni = 0; ni < 8; ni++) {
                float* a = acc[mi][ni];
                int m = m0 + warp_m * 64 + mi * 16 + rI;
                int n = n0 + warp_n * 64 + ni * 8 + cI;
                __half h0, l0, h1, l1;
                split2h(a[0], h0, l0); split2h(a[1], h1, l1);
                *(__half2*)(Oh + (size_t)m * ldo + n) = __half2{h0, h1};
                *(__half2*)(Ol + (size_t)m * ldo + n) = __half2{l0, l1};
                split2h(a[2], h0, l0); split2h(a[3], h1, l1);
                *(__half2*)(Oh + (size_t)(m + 8) * ldo + n) = __half2{h0, h1};
                *(__half2*)(Ol + (size_t)(m + 8) * ldo + n) = __half2{l0, l1};
            }
    } else {  // EPI == 5: fp16 dual transposed (via fp32 smem)
        __syncthreads();
        float* T = (float*)smem_raw;      // [128][132] fp32 = 67584 B < SMEM_SZ0
#pragma unroll
        for (int mi = 0; mi < 4; mi++)
#pragma unroll
            for (int ni = 0; ni < 8; ni++) {
                float* a = acc[mi][ni];
                int lm = warp_m * 64 + mi * 16 + rI;
                int ln = warp_n * 64 + ni * 8 + cI;
                T[lm * 132 + ln]           = a[0];
                T[lm * 132 + ln + 1]       = a[1];
                T[(lm + 8) * 132 + ln]     = a[2];
                T[(lm + 8) * 132 + ln + 1] = a[3];
            }
        __syncthreads();
        __half* Oh = (__half*)O0;
        __half* Ol = (__half*)O1;
        const int n = tid;                // one output row per thread
#pragma unroll
        for (int i = 0; i < 128; i += 8) {
            __half hp[8], lp[8];
#pragma unroll
            for (int j = 0; j < 8; j++) {
                split2h(T[(i + j) * 132 + n], hp[j], lp[j]);
            }
            size_t o = (size_t)(n0 + n) * ldo + m0 + i;
            *(uint4*)(Oh + o) = *(uint4*)hp;
            *(uint4*)(Ol + o) = *(uint4*)lp;
        }
    }
}

// ---------------------------------------------------------------------------
// Stage 0a: split x -> bf16 hi/lo
// ---------------------------------------------------------------------------
__global__ __launch_bounds__(256) void k_convx(const float* __restrict__ x)
{
    size_t i = ((size_t)blockIdx.x * 256 + threadIdx.x) * 4;
    float4 v = *(const float4*)(x + i);
    __nv_bfloat16 h0, l0, h1, l1, h2, l2, h3, l3;
    split2(v.x, h0, l0); split2(v.y, h1, l1);
    split2(v.z, h2, l2); split2(v.w, h3, l3);
    __nv_bfloat162 a{h0, h1}, b{h2, h3};
    *(__nv_bfloat162*)(g_xhi + i)     = a;
    *(__nv_bfloat162*)(g_xhi + i + 2) = b;
    a = {l0, l1}; b = {l2, l3};
    *(__nv_bfloat162*)(g_xlo + i)     = a;
    *(__nv_bfloat162*)(g_xlo + i + 2) = b;
}

// ---------------------------------------------------------------------------
// Stage 0b: transpose + split W[D,H] -> WT hi/lo [H,D]
// ---------------------------------------------------------------------------
__global__ __launch_bounds__(256) void k_convw(
    const float* __restrict__ Wq, const float* __restrict__ Wk,
    const float* __restrict__ Wv)
{
    __shared__ float t[32][33];
    const int z = blockIdx.z;
    const float* W = (z == 0) ? Wq : (z == 1) ? Wk : Wv;
    __nv_bfloat16* Oh = g_wthi[z];
    __nv_bfloat16* Ol = g_wtlo[z];
    const int h0 = blockIdx.x * 32, d0 = blockIdx.y * 32;
    const int tx = threadIdx.x, ty = threadIdx.y;

    for (int i = ty; i < 32; i += 8)
        t[i][tx] = W[(size_t)(d0 + i) * H + h0 + tx];
    __syncthreads();
    for (int i = ty; i < 32; i += 8) {
        float v = t[tx][i];
        __nv_bfloat16 h, l;
        split2(v, h, l);
        Oh[(size_t)(h0 + i) * D + d0 + tx] = h;
        Ol[(size_t)(h0 + i) * D + d0 + tx] = l;
    }
}

// ---------------------------------------------------------------------------
// Stage 1: q (fp16 single), k (fp16 dual), v (fp16 dual transposed)
// ---------------------------------------------------------------------------
__global__ __launch_bounds__(NT, 2) void k_qkv()
{
    const int z = blockIdx.z;
    const int m0 = blockIdx.y * 128, n0 = blockIdx.x * 128;
    if (z == 0) {
        gemm128<3, 0>(g_xhi, g_xlo, D, g_wthi[0], g_wtlo[0], D,
                      (void*)g_qh, nullptr, H, 1.0f, m0, n0, 0, D);
    } else if (z == 1) {
        gemm128<4, 0>(g_xhi, g_xlo, D, g_wthi[1], g_wtlo[1], D,
                      (void*)g_kh, (void*)g_kl, H, 1.0f, m0, n0, 0, D);
    } else {
        gemm128<5, 0>(g_xhi, g_xlo, D, g_wthi[2], g_wtlo[2], D,
                      (void*)g_vth, (void*)g_vtl, L, 1.0f, m0, n0, 0, D);
    }
}

// ---------------------------------------------------------------------------
// Stage 2: S = (q @ k^T)/32, lower-triangular tiles, fp16 2-pass
// ---------------------------------------------------------------------------
__global__ __launch_bounds__(NT, 2) void k_scores()
{
    if (blockIdx.x > blockIdx.y) return;
    gemm128<2, 1>(g_qh, g_qh, H, g_kh, g_kl, H,
                  (void*)g_s, nullptr, L, 0.03125f,
                  blockIdx.y * 128, blockIdx.x * 128, 0, H);
}

// ---------------------------------------------------------------------------
// Stage 3: row softmax over cols [0, r]; single g_s read (register cache);
// write P as fp16 single, zero-fill to 128-block end.
// ---------------------------------------------------------------------------
__global__ __launch_bounds__(256) void k_softmax()
{
    __shared__ float red[256];
    const int r   = blockIdx.x;
    const int n   = r + 1;
    const int tid = threadIdx.x;
    const float* row = g_s + (size_t)r * L;
    __half* p = g_p + (size_t)r * L;

    float xv[16];
#pragma unroll
    for (int j = 0; j < 16; j++) {
        int i = tid + j * 256;
        xv[j] = (i < n) ? row[i] : -3.4e38f;
    }
    float m = -3.4e38f;
#pragma unroll
    for (int j = 0; j < 16; j++) m = fmaxf(m, xv[j]);
    red[tid] = m;
    __syncthreads();
    for (int s = 128; s > 0; s >>= 1) {
        if (tid < s) red[tid] = fmaxf(red[tid], red[tid + s]);
        __syncthreads();
    }
    m = red[0];
    __syncthreads();

    float ev[16];
    float acc = 0.0f;
#pragma unroll
    for (int j = 0; j < 16; j++) {
        ev[j] = __expf(xv[j] - m);   // -inf-ish -> 0
        acc += ev[j];
    }
    red[tid] = acc;
    __syncthreads();
    for (int s = 128; s > 0; s >>= 1) {
        if (tid < s) red[tid] += red[tid + s];
        __syncthreads();
    }
    const float inv = 1.0f / red[0];

#pragma unroll
    for (int j = 0; j < 16; j++) {
        int i = tid + j * 256;
        if (i < n) p[i] = __float2half_rn(ev[j] * inv);
    }
    const int blockEnd = ((r >> 7) + 1) << 7;
    for (int i = n + tid; i < blockEnd; i += 256) p[i] = __half(0.0f);
}

// ---------------------------------------------------------------------------
// Stage 4: out = P @ v (k truncated at diagonal block), split-K for bi>=16.
// ---------------------------------------------------------------------------
__global__ __launch_bounds__(NT, 2) void k_pv(float* __restrict__ out)
{
    const int y = blockIdx.y;
    int bi, kb, ke;
    float* dst;
    if (y < 16) {
        bi = y; kb = 0; ke = (bi + 1) * 128; dst = out;
    } else {
        const int p = y - 16;
        bi = 16 + (p >> 1);
        const int tot = (bi + 1) * 128;
        const int k0  = ((bi + 1) >> 1) * 128;
        if (p & 1) { kb = k0; ke = tot; dst = out; }
        else       { kb = 0;  ke = k0;  dst = (float*)g_s; }
    }
    gemm128<2, 1>(g_p, g_p, L, g_vth, g_vtl, L,
                  (void*)dst, nullptr, H, 1.0f,
                  bi * 128, blockIdx.x * 128, kb, ke);
}

__global__ __launch_bounds__(256) void k_pvadd(float* __restrict__ out)
{
    size_t i = (size_t)2048 * H + ((size_t)blockIdx.x * 256 + threadIdx.x) * 4;
    float4 a = *(float4*)(out + i);
    float4 b = *(const float4*)(g_s + i);
    a.x += b.x; a.y += b.y; a.z += b.z; a.w += b.w;
    *(float4*)(out + i) = a;
}

// ---------------------------------------------------------------------------
extern "C" void kernel_launch(void* const* d_in, const int* in_sizes, int n_in,
                              void* d_out, int out_size)
{
    const float* x  = (const float*)d_in[0];
    // d_in[1] = mask (structurally triu(k=1); causality handled directly)
    const float* Wq = (const float*)d_in[2];
    const float* Wk = (const float*)d_in[3];
    const float* Wv = (const float*)d_in[4];
    float* out = (float*)d_out;

    cudaFuncSetAttribute(k_qkv,    cudaFuncAttributeMaxDynamicSharedMemorySize, SMEM_SZ0);
    cudaFuncSetAttribute(k_scores, cudaFuncAttributeMaxDynamicSharedMemorySize, SMEM_SZ1);
    cudaFuncSetAttribute(k_pv,     cudaFuncAttributeMaxDynamicSharedMemorySize, SMEM_SZ1);

    k_convx<<<(L * D) / 1024, 256>>>(x);
    k_convw<<<dim3(H / 32, D / 32, 3), dim3(32, 8)>>>(Wq, Wk, Wv);
    k_qkv<<<dim3(H / 128, L / 128, 3), NT, SMEM_SZ0>>>();
    k_scores<<<dim3(L / 128, L / 128), NT, SMEM_SZ1>>>();
    k_softmax<<<L, 256>>>();
    k_pv<<<dim3(H / 128, 48), NT, SMEM_SZ1>>>(out);
    k_pvadd<<<(2048 * H) / 1024, 256>>>(out);
}

// round 8
// speedup vs baseline: 3.2654x; 2.0038x over previous
#include <cuda_runtime.h>
#include <cuda_fp16.h>

#define L 4096
#define D 1024
#define H 1024

// ---------------------------------------------------------------------------
// Scratch (__device__ globals; allocation-free rule)
// ---------------------------------------------------------------------------
__device__ __half g_x[(size_t)L * D];          // x, fp16
__device__ __half g_wt[3][(size_t)H * D];      // 32*W transposed, fp16
__device__ __half g_q[(size_t)L * H];          // q fp16
__device__ __half g_k[(size_t)L * H];          // k fp16
__device__ __half g_vt[(size_t)H * L];         // v transposed fp16 [H][L]
__device__ float  g_s[(size_t)L * L];          // scores; later PV split-K partials
__device__ __half g_p[(size_t)L * L];          // softmax P fp16

// ---------------------------------------------------------------------------
// Helpers
// ---------------------------------------------------------------------------
__device__ __forceinline__ unsigned smem_u32(const void* p) {
    unsigned a;
    asm("{ .reg .u64 t; cvta.to.shared.u64 t, %1; cvt.u32.u64 %0, t; }"
        : "=r"(a) : "l"(p));
    return a;
}

__device__ __forceinline__ void cpa16(unsigned dst, const void* src) {
    asm volatile("cp.async.cg.shared.global [%0], [%1], 16;"
                 :: "r"(dst), "l"(src) : "memory");
}
__device__ __forceinline__ void cpa_commit() {
    asm volatile("cp.async.commit_group;" ::: "memory");
}
template <int N>
__device__ __forceinline__ void cpa_wait() {
    asm volatile("cp.async.wait_group %0;" :: "n"(N) : "memory");
}

__device__ __forceinline__ void ldsm4(unsigned& r0, unsigned& r1, unsigned& r2,
                                      unsigned& r3, unsigned addr) {
    asm volatile("ldmatrix.sync.aligned.m8n8.x4.shared.b16 {%0,%1,%2,%3}, [%4];"
                 : "=r"(r0), "=r"(r1), "=r"(r2), "=r"(r3) : "r"(addr));
}

__device__ __forceinline__ void mma_fp(float* c, const unsigned* a,
                                       unsigned b0, unsigned b1) {
    asm volatile(
        "mma.sync.aligned.m16n8k16.row.col.f32.f16.f16.f32 "
        "{%0,%1,%2,%3}, {%4,%5,%6,%7}, {%8,%9}, {%0,%1,%2,%3};"
        : "+f"(c[0]), "+f"(c[1]), "+f"(c[2]), "+f"(c[3])
        : "r"(a[0]), "r"(a[1]), "r"(a[2]), "r"(a[3]), "r"(b0), "r"(b1));
}

// ---------------------------------------------------------------------------
// Single-fp16 128x128 GEMM-NT: C = alpha * (A @ B^T), K range [kBeg, kEnd).
// 128 threads, 4 warps (2x2), warp tile 64x64; pad-80 smem rows; BK=32;
// 2-stage cp.async with load-after-compute; 2 CTAs/SM.
// EPI: 2 = fp32*alpha row-major | 3 = fp16*alpha row-major
//      5 = fp16*alpha TRANSPOSED (via fp32 smem staging)
// ---------------------------------------------------------------------------
#define TILE_B    10240            // 128 rows x 40 halves (pad) = 10240 B
#define STAGE_B   (2 * TILE_B)     // A, B
#define NT        128
#define SMEM_G    (2 * STAGE_B)    // 40960  (scores / pv)
#define SMEM_QKV  67584            // transpose staging [128][132] fp32

template <int EPI>
__device__ __forceinline__ void gemm128(
    const __half* __restrict__ A, int lda,
    const __half* __restrict__ B, int ldb,
    void* O0, int ldo, float alpha,
    int m0, int n0, int kBeg, int kEnd)
{
    extern __shared__ char smem_raw[];
    const unsigned sbase = smem_u32(smem_raw);

    const int tid    = threadIdx.x;
    const int wid    = tid >> 5;
    const int lane   = tid & 31;
    const int warp_m = wid >> 1;          // 0..1 (64 rows)
    const int warp_n = wid & 1;           // 0..1 (64 cols)

    const char* pA = (const char*)(A + (size_t)m0 * lda + kBeg);
    const char* pB = (const char*)(B + (size_t)n0 * ldb + kBeg);

    const int nc = (kEnd - kBeg) >> 5;    // BK=32 chunks

    // ---- loader: 4 threads/row, 4 row-passes, 2 tiles ----
    const int lr0 = tid >> 2;             // 0..31
    const int lcc = tid & 3;              // 16B chunk in row
    auto load_stage = [&](int s) {
        unsigned sb = sbase + (unsigned)(s & 1) * STAGE_B;
        const size_t kof = (size_t)s * 64 + lcc * 16;   // bytes
#pragma unroll
        for (int j = 0; j < 4; j++) {
            int r = lr0 + j * 32;
            unsigned so = (unsigned)(r * 80 + lcc * 16);
            cpa16(sb + so,          pA + (size_t)r * lda * 2 + kof);
            cpa16(sb + TILE_B + so, pB + (size_t)r * ldb * 2 + kof);
        }
    };

    // ---- fragment address bases ----
    const unsigned aRowOff =
        (unsigned)((warp_m * 64 + (lane & 15)) * 80 + (lane >> 4) * 16);
    const unsigned bRowOff =
        (unsigned)((warp_n * 64 + (lane & 7) + (lane >> 4) * 8) * 80
                   + ((lane >> 3) & 1) * 16);

    float acc[4][8][4];
#pragma unroll
    for (int i = 0; i < 4; i++)
#pragma unroll
        for (int j = 0; j < 8; j++)
#pragma unroll
            for (int k = 0; k < 4; k++) acc[i][j][k] = 0.0f;

    load_stage(0); cpa_commit();
    if (nc > 1) load_stage(1);
    cpa_commit();

    for (int c = 0; c < nc; c++) {
        cpa_wait<1>();
        __syncthreads();

        const unsigned sb  = sbase + (unsigned)(c & 1) * STAGE_B;
        const unsigned sbB = sb + TILE_B;
#pragma unroll
        for (int ks = 0; ks < 2; ks++) {
            unsigned bh[4][4];
#pragma unroll
            for (int g = 0; g < 4; g++) {
                unsigned bd = sbB + bRowOff + g * 1280 + ks * 32;
                ldsm4(bh[g][0], bh[g][1], bh[g][2], bh[g][3], bd);
            }
#pragma unroll
            for (int mi = 0; mi < 4; mi++) {
                unsigned ah[4];
                unsigned ad = sb + aRowOff + mi * 1280 + ks * 32;
                ldsm4(ah[0], ah[1], ah[2], ah[3], ad);
#pragma unroll
                for (int ni = 0; ni < 8; ni++)
                    mma_fp(acc[mi][ni], ah,
                           bh[ni >> 1][(ni & 1) * 2], bh[ni >> 1][(ni & 1) * 2 + 1]);
            }
        }

        __syncthreads();                    // reads of buffer (c&1) done
        if (c + 2 < nc) load_stage(c + 2);  // overwrites buffer (c&1)
        cpa_commit();
    }

    // ---- epilogue ----
    const int rI = lane >> 2;
    const int cI = (lane & 3) * 2;

    if (EPI == 2) {
        float* O = (float*)O0;
#pragma unroll
        for (int mi = 0; mi < 4; mi++)
#pragma unroll
            for (int ni = 0; ni < 8; ni++) {
                float* a = acc[mi][ni];
                int m = m0 + warp_m * 64 + mi * 16 + rI;
                int n = n0 + warp_n * 64 + ni * 8 + cI;
                float2 v0 = {a[0] * alpha, a[1] * alpha};
                float2 v1 = {a[2] * alpha, a[3] * alpha};
                *(float2*)(O + (size_t)m * ldo + n) = v0;
                *(float2*)(O + (size_t)(m + 8) * ldo + n) = v1;
            }
    } else if (EPI == 3) {
        __half* O = (__half*)O0;
#pragma unroll
        for (int mi = 0; mi < 4; mi++)
#pragma unroll
            for (int ni = 0; ni < 8; ni++) {
                float* a = acc[mi][ni];
                int m = m0 + warp_m * 64 + mi * 16 + rI;
                int n = n0 + warp_n * 64 + ni * 8 + cI;
                *(__half2*)(O + (size_t)m * ldo + n) =
                    __floats2half2_rn(a[0] * alpha, a[1] * alpha);
                *(__half2*)(O + (size_t)(m + 8) * ldo + n) =
                    __floats2half2_rn(a[2] * alpha, a[3] * alpha);
            }
    } else {  // EPI == 5: fp16 single transposed (via fp32 smem)
        __syncthreads();
        float* T = (float*)smem_raw;      // [128][132] fp32 = 67584 B
#pragma unroll
        for (int mi = 0; mi < 4; mi++)
#pragma unroll
            for (int ni = 0; ni < 8; ni++) {
                float* a = acc[mi][ni];
                int lm = warp_m * 64 + mi * 16 + rI;
                int ln = warp_n * 64 + ni * 8 + cI;
                T[lm * 132 + ln]           = a[0];
                T[lm * 132 + ln + 1]       = a[1];
                T[(lm + 8) * 132 + ln]     = a[2];
                T[(lm + 8) * 132 + ln + 1] = a[3];
            }
        __syncthreads();
        __half* O = (__half*)O0;
        const int n = tid;                // one output row per thread
#pragma unroll
        for (int i = 0; i < 128; i += 8) {
            __half hp[8];
#pragma unroll
            for (int j = 0; j < 8; j++)
                hp[j] = __float2half_rn(T[(i + j) * 132 + n] * alpha);
            size_t o = (size_t)(n0 + n) * ldo + m0 + i;
            *(uint4*)(O + o) = *(uint4*)hp;
        }
    }
}

// ---------------------------------------------------------------------------
// Stage 0a: x fp32 -> fp16
// ---------------------------------------------------------------------------
__global__ __launch_bounds__(256) void k_convx(const float* __restrict__ x)
{
    size_t i = ((size_t)blockIdx.x * 256 + threadIdx.x) * 4;
    float4 v = *(const float4*)(x + i);
    *(__half2*)(g_x + i)     = __floats2half2_rn(v.x, v.y);
    *(__half2*)(g_x + i + 2) = __floats2half2_rn(v.z, v.w);
}

// ---------------------------------------------------------------------------
// Stage 0b: transpose W[D,H] -> WT[H,D] fp16, prescaled by 32
// ---------------------------------------------------------------------------
__global__ __launch_bounds__(256) void k_convw(
    const float* __restrict__ Wq, const float* __restrict__ Wk,
    const float* __restrict__ Wv)
{
    __shared__ float t[32][33];
    const int z = blockIdx.z;
    const float* W = (z == 0) ? Wq : (z == 1) ? Wk : Wv;
    __half* O = g_wt[z];
    const int h0 = blockIdx.x * 32, d0 = blockIdx.y * 32;
    const int tx = threadIdx.x, ty = threadIdx.y;

    for (int i = ty; i < 32; i += 8)
        t[i][tx] = W[(size_t)(d0 + i) * H + h0 + tx];
    __syncthreads();
    for (int i = ty; i < 32; i += 8)
        O[(size_t)(h0 + i) * D + d0 + tx] = __float2half_rn(t[tx][i] * 32.0f);
}

// ---------------------------------------------------------------------------
// Stage 1: q,k (fp16 row-major), v (fp16 transposed); alpha=1/32 (W prescale)
// ---------------------------------------------------------------------------
__global__ __launch_bounds__(NT, 2) void k_qkv()
{
    const int z = blockIdx.z;
    const int m0 = blockIdx.y * 128, n0 = blockIdx.x * 128;
    if (z == 0) {
        gemm128<3>(g_x, D, g_wt[0], D, (void*)g_q, H, 0.03125f, m0, n0, 0, D);
    } else if (z == 1) {
        gemm128<3>(g_x, D, g_wt[1], D, (void*)g_k, H, 0.03125f, m0, n0, 0, D);
    } else {
        gemm128<5>(g_x, D, g_wt[2], D, (void*)g_vt, L, 0.03125f, m0, n0, 0, D);
    }
}

// ---------------------------------------------------------------------------
// Stage 2: S = (q @ k^T)/32, lower-triangular tiles, 1-pass fp16
// ---------------------------------------------------------------------------
__global__ __launch_bounds__(NT, 2) void k_scores()
{
    if (blockIdx.x > blockIdx.y) return;
    gemm128<2>(g_q, H, g_k, H, (void*)g_s, L, 0.03125f,
               blockIdx.y * 128, blockIdx.x * 128, 0, H);
}

// ---------------------------------------------------------------------------
// Stage 3: row softmax over cols [0, r] (register-cached single pass);
// write P fp16, zero-fill to 128-block end.
// ---------------------------------------------------------------------------
__global__ __launch_bounds__(256) void k_softmax()
{
    __shared__ float red[256];
    const int r   = blockIdx.x;
    const int n   = r + 1;
    const int tid = threadIdx.x;
    const float* row = g_s + (size_t)r * L;
    __half* p = g_p + (size_t)r * L;

    float xv[16];
#pragma unroll
    for (int j = 0; j < 16; j++) {
        int i = tid + j * 256;
        xv[j] = (i < n) ? row[i] : -3.4e38f;
    }
    float m = -3.4e38f;
#pragma unroll
    for (int j = 0; j < 16; j++) m = fmaxf(m, xv[j]);
    red[tid] = m;
    __syncthreads();
    for (int s = 128; s > 0; s >>= 1) {
        if (tid < s) red[tid] = fmaxf(red[tid], red[tid + s]);
        __syncthreads();
    }
    m = red[0];
    __syncthreads();

    float ev[16];
    float acc = 0.0f;
#pragma unroll
    for (int j = 0; j < 16; j++) {
        ev[j] = __expf(xv[j] - m);
        acc += ev[j];
    }
    red[tid] = acc;
    __syncthreads();
    for (int s = 128; s > 0; s >>= 1) {
        if (tid < s) red[tid] += red[tid + s];
        __syncthreads();
    }
    const float inv = 1.0f / red[0];

#pragma unroll
    for (int j = 0; j < 16; j++) {
        int i = tid + j * 256;
        if (i < n) p[i] = __float2half_rn(ev[j] * inv);
    }
    const int blockEnd = ((r >> 7) + 1) << 7;
    for (int i = n + tid; i < blockEnd; i += 256) p[i] = __half(0.0f);
}

// ---------------------------------------------------------------------------
// Stage 4: out = P @ v (k truncated at diagonal block), split-K for bi>=16.
// ---------------------------------------------------------------------------
__global__ __launch_bounds__(NT, 2) void k_pv(float* __restrict__ out)
{
    const int y = blockIdx.y;
    int bi, kb, ke;
    float* dst;
    if (y < 16) {
        bi = y; kb = 0; ke = (bi + 1) * 128; dst = out;
    } else {
        const int p = y - 16;
        bi = 16 + (p >> 1);
        const int tot = (bi + 1) * 128;
        const int k0  = ((bi + 1) >> 1) * 128;
        if (p & 1) { kb = k0; ke = tot; dst = out; }
        else       { kb = 0;  ke = k0;  dst = (float*)g_s; }
    }
    gemm128<2>(g_p, L, g_vt, L, (void*)dst, H, 1.0f,
               bi * 128, blockIdx.x * 128, kb, ke);
}

__global__ __launch_bounds__(256) void k_pvadd(float* __restrict__ out)
{
    size_t i = (size_t)2048 * H + ((size_t)blockIdx.x * 256 + threadIdx.x) * 4;
    float4 a = *(float4*)(out + i);
    float4 b = *(const float4*)(g_s + i);
    a.x += b.x; a.y += b.y; a.z += b.z; a.w += b.w;
    *(float4*)(out + i) = a;
}

// ---------------------------------------------------------------------------
extern "C" void kernel_launch(void* const* d_in, const int* in_sizes, int n_in,
                              void* d_out, int out_size)
{
    const float* x  = (const float*)d_in[0];
    // d_in[1] = mask (structurally triu(k=1); causality handled directly)
    const float* Wq = (const float*)d_in[2];
    const float* Wk = (const float*)d_in[3];
    const float* Wv = (const float*)d_in[4];
    float* out = (float*)d_out;

    cudaFuncSetAttribute(k_qkv,    cudaFuncAttributeMaxDynamicSharedMemorySize, SMEM_QKV);
    cudaFuncSetAttribute(k_scores, cudaFuncAttributeMaxDynamicSharedMemorySize, SMEM_G);
    cudaFuncSetAttribute(k_pv,     cudaFuncAttributeMaxDynamicSharedMemorySize, SMEM_G);

    k_convx<<<(L * D) / 1024, 256>>>(x);
    k_convw<<<dim3(H / 32, D / 32, 3), dim3(32, 8)>>>(Wq, Wk, Wv);
    k_qkv<<<dim3(H / 128, L / 128, 3), NT, SMEM_QKV>>>();
    k_scores<<<dim3(L / 128, L / 128), NT, SMEM_G>>>();
    k_softmax<<<L, 256>>>();
    k_pv<<<dim3(H / 128, 48), NT, SMEM_G>>>(out);
    k_pvadd<<<(2048 * H) / 1024, 256>>>(out);
}